// round 5
// baseline (speedup 1.0000x reference)
#include <cuda_runtime.h>

#define BN 64
#define TN 512
#define LN 48
#define START_I 46
#define PAD_I 45
#define END_I 47

__device__ float g_fs_end[BN];
__device__ float g_tg[BN];
__device__ unsigned int g_done;   // zero-init; self-resetting arrival counter

#define FMA_F32X2(d, a, b, c) \
    asm("fma.rn.f32x2 %0, %1, %2, %3;" : "=l"(d) : "l"(a), "l"(b), "l"(c))
#define ADD_F32X2_(d, a, b) \
    asm("add.rn.f32x2 %0, %1, %2;" : "=l"(d) : "l"(a), "l"(b))
#define PACK_F32X2_(d, lo, hi) \
    asm("mov.b64 %0, {%1, %2};" : "=l"(d) : "f"(lo), "f"(hi))
#define UNPACK_F32X2_(lo, hi, s) \
    asm("mov.b64 {%0, %1}, %2;" : "=f"(lo), "=f"(hi) : "l"(s))

// One block per batch, 64 threads (2 warps); thread j < 48 owns column j.
// State kept in scaled linear domain: u_j = exp(fs_j - K*ln2).
//   w_i   = u_i * es_i * 2^{-k}          (es = exp(scores), k = lag-2 exponent of u_0)
//   u_j  <- sum_i w_i * E[i,j]           (E = exp(trans), constant, in registers)
// No exp/log in the loop: rescale exponent comes from float bit tricks.
__global__ __launch_bounds__(64, 1) void crf_scan_kernel(
    const float* __restrict__ scores,
    const int* __restrict__ mask,
    const float* __restrict__ trans)
{
    const int b   = blockIdx.x;
    const int tid = threadIdx.x;
    const bool act = (tid < LN);
    const int j   = act ? tid : 0;

    __shared__ __align__(16) float sh_w[2][LN];
    __shared__ int sh_k[2];

    // E column j, packed as 24 f32x2 pairs (i, i+1); exp(-10000) == 0
    unsigned long long Ep[LN / 2];
#pragma unroll
    for (int q = 0; q < LN / 2; q++) {
        float lo = __expf(trans[(2 * q) * LN + j]);
        float hi = __expf(trans[(2 * q + 1) * LN + j]);
        PACK_F32X2_(Ep[q], lo, hi);
    }

    // init: fs_j = trans[START, j]  ->  u_j = exp(trans[START, j]) (== 1), K = 0
    float u = __expf(trans[START_I * LN + j]);
    int K = 0;
    int kcur = 0;

    if (tid == 0) { sh_k[0] = 0; sh_k[1] = 0; }

    const float* scp = scores + (size_t)b * TN * LN + j;
    const int*   mp  = mask + (size_t)b * TN;

    // depth-4 prefetch of es = exp(score) and mask (MUFU off the critical path)
    float es[4];
    int   mb[4];
#pragma unroll
    for (int q = 0; q < 4; q++) { es[q] = __expf(scp[q * LN]); mb[q] = mp[q]; }

    float w = u * es[0];       // step-0 input (scale 2^0)
    __syncthreads();

    for (int t0 = 0; t0 < TN; t0 += 4) {
#pragma unroll
        for (int k = 0; k < 4; k++) {
            const int t = t0 + k;
            const int p = t & 1;
            const int msk = mb[k];

            if (act) sh_w[p][j] = w;
            __syncthreads();

            K += kcur;
            const float sc_cur = __int_as_float((127 - kcur) << 23);

            // matvec: acc = sum_i w_i * E[i,j], via 24 packed FFMA2
            const ulonglong2* w2 = (const ulonglong2*)sh_w[p];
            unsigned long long a0 = 0ull, a1 = 0ull, a2 = 0ull, a3 = 0ull;
#pragma unroll
            for (int q = 0; q < LN / 4; q++) {      // 12 LDS.128, 24 FFMA2
                const ulonglong2 wq = w2[q];
                switch (q & 1) {
                  case 0:
                    FMA_F32X2(a0, wq.x, Ep[2 * q],     a0);
                    FMA_F32X2(a1, wq.y, Ep[2 * q + 1], a1);
                    break;
                  default:
                    FMA_F32X2(a2, wq.x, Ep[2 * q],     a2);
                    FMA_F32X2(a3, wq.y, Ep[2 * q + 1], a3);
                    break;
                }
            }
            unsigned long long s01, s23, s;
            ADD_F32X2_(s01, a0, a1);
            ADD_F32X2_(s23, a2, a3);
            ADD_F32X2_(s, s01, s23);
            float slo, shi;
            UNPACK_F32X2_(slo, shi, s);
            const float accv = slo + shi;

            const float u_new = msk ? accv : u * sc_cur;

            // publish exponent of u_0 (thread 0); consumed at step t+2
            if (tid == 0) sh_k[p] = (__float_as_int(u_new) >> 23) - 127;

            // tail: build next step's w entirely here (scale written at t-1)
            const int knext = sh_k[p ^ 1];
            const float scn = __int_as_float((127 - knext) << 23);
            u = u_new;
            w = u * es[(k + 1) & 3] * scn;
            kcur = knext;

            if (t0 + 4 < TN) {
                es[k] = __expf(scp[(t0 + 4 + k) * LN]);
                mb[k] = mp[t0 + 4 + k];
            }
        }
    }

    if (tid == END_I) g_fs_end[b] = (float)K * 0.6931471805599453f + logf(u);
}

// gold-path energy per batch + fused final reduction (last block reduces).
// gold_target is declared int64 but JAX (x64 off) materializes int32 — detect.
__global__ void crf_tg_final_kernel(
    const float* __restrict__ scores,
    const void* __restrict__ gold_raw,
    const int* __restrict__ mask,
    const float* __restrict__ trans,
    float* __restrict__ out)
{
    const int b = blockIdx.x;
    const int tid = threadIdx.x;
    __shared__ float red[256];
    __shared__ int s_is64;

    const int* g32 = (const int*)gold_raw;
    if (tid == 0) {
        int all0 = 1;
        for (int q = 0; q < 64; q++) all0 &= (g32[2 * q + 1] == 0);
        s_is64 = all0;
    }
    __syncthreads();
    const int is64 = s_is64;

    float sum = 0.f;
    for (int t = tid; t < TN; t += 256) {
        const long long li = (long long)b * TN + t;
        const int g = is64 ? g32[2 * li] : g32[li];     // little-endian low word
        const float v = scores[li * LN] + trans[g];     // crf[t+1,b,0,g]
        if (mask[li]) sum += v;
    }
    if (tid == 0) sum += trans[START_I];  // t=0 term: trans[0][START]

    red[tid] = sum;
    __syncthreads();
    for (int s = 128; s > 0; s >>= 1) {
        if (tid < s) red[tid] += red[tid + s];
        __syncthreads();
    }
    if (tid == 0) {
        g_tg[b] = red[0];
        __threadfence();
        const unsigned r = atomicAdd(&g_done, 1u);
        if (r == BN - 1) {               // last block: deterministic final combine
            float f = 0.f, tg = 0.f;
            for (int i = 0; i < BN; i++) { f += g_fs_end[i]; tg += g_tg[i]; }
            out[0] = (f - tg) / (float)BN;
            g_done = 0u;                 // reset for next graph replay
        }
    }
}

extern "C" void kernel_launch(void* const* d_in, const int* in_sizes, int n_in,
                              void* d_out, int out_size)
{
    const float* scores = (const float*)d_in[0];
    const void*  gold   = (const void*)d_in[1];
    const int*   mask   = (const int*)d_in[2];
    const float* trans  = (const float*)d_in[3];
    float*       out    = (float*)d_out;

    crf_scan_kernel<<<BN, 64>>>(scores, mask, trans);
    crf_tg_final_kernel<<<BN, 256>>>(scores, gold, mask, trans, out);
}

// round 6
// speedup vs baseline: 1.1638x; 1.1638x over previous
#include <cuda_runtime.h>

#define BN 64
#define TN 512
#define LN 48
#define START_I 46
#define PAD_I 45
#define END_I 47

__device__ float g_val[BN];
__device__ unsigned int g_done;   // zero-init; self-resetting arrival counter

#define FMA_F32X2(d, a, b, c) \
    asm("fma.rn.f32x2 %0, %1, %2, %3;" : "=l"(d) : "l"(a), "l"(b), "l"(c))
#define ADD_F32X2_(d, a, b) \
    asm("add.rn.f32x2 %0, %1, %2;" : "=l"(d) : "l"(a), "l"(b))
#define PACK_F32X2_(d, lo, hi) \
    asm("mov.b64 %0, {%1, %2};" : "=l"(d) : "f"(lo), "f"(hi))
#define UNPACK_F32X2_(lo, hi, s) \
    asm("mov.b64 {%0, %1}, %2;" : "=f"(lo), "=f"(hi) : "l"(s))

// Named barriers: scan warps (0-1) use id 1 / 64 threads; tg warps (2-3) id 2 / 64.
#define BAR_SCAN() asm volatile("bar.sync 1, 64;" ::: "memory")
#define BAR_TG()   asm volatile("bar.sync 2, 64;" ::: "memory")

// One block per batch, 128 threads.
//   warps 0-1 (tid 0..63): forward scan, thread j < 48 owns column j.
//     State in scaled linear domain: u_j = exp(fs_j - K*ln2).
//       w_i  = u_i * es_i * 2^{-k}     (es = exp(scores), k = lagged exponent of u_0)
//       u_j <- sum_i w_i * E[i,j]      (E = exp(trans), registers, 24 packed f32x2)
//     No exp/log inside the loop.
//   warps 2-3 (tid 64..127): gold-path energy for the same batch (runs concurrently,
//     finishes early, parks at the final __syncthreads).
__global__ __launch_bounds__(128, 1) void crf_fused_kernel(
    const float* __restrict__ scores,
    const void* __restrict__ gold_raw,
    const int* __restrict__ mask,
    const float* __restrict__ trans,
    float* __restrict__ out)
{
    const int b   = blockIdx.x;
    const int tid = threadIdx.x;

    __shared__ __align__(16) float sh_w[2][LN];
    __shared__ int sh_k[2];
    __shared__ float sh_fs;       // scan result: fs_END
    __shared__ float sh_tgp[2];   // tg per-warp partials
    __shared__ int s_is64;

    if (tid < 64) {
        // ---------------- scan group ----------------
        const bool act = (tid < LN);
        const int j    = act ? tid : 0;

        // E column j, packed as 24 f32x2 pairs (i, i+1); exp(-10000) == 0
        unsigned long long Ep[LN / 2];
#pragma unroll
        for (int q = 0; q < LN / 2; q++) {
            float lo = __expf(trans[(2 * q) * LN + j]);
            float hi = __expf(trans[(2 * q + 1) * LN + j]);
            PACK_F32X2_(Ep[q], lo, hi);
        }

        // init: fs_j = trans[START, j] -> u_j = exp(.), K = 0
        float u = __expf(trans[START_I * LN + j]);
        int K = 0;
        int kcur = 0;

        if (tid == 0) { sh_k[0] = 0; sh_k[1] = 0; }

        const float* scp = scores + (size_t)b * TN * LN + j;
        const int*   mp  = mask + (size_t)b * TN;

        // depth-4 prefetch of es = exp(score) and mask
        float es[4];
        int   mb[4];
#pragma unroll
        for (int q = 0; q < 4; q++) { es[q] = __expf(scp[q * LN]); mb[q] = mp[q]; }

        float w = u * es[0];      // step-0 input (scale 2^0)
        BAR_SCAN();

        for (int t0 = 0; t0 < TN; t0 += 4) {
#pragma unroll
            for (int k = 0; k < 4; k++) {
                const int t = t0 + k;
                const int p = t & 1;
                const int msk = mb[k];

                if (act) sh_w[p][j] = w;
                BAR_SCAN();

                // next-step scale: knext published one step ago; fold into es NOW
                // (independent of the matvec -> off the critical path)
                const int knext = sh_k[p ^ 1];
                const float esn = es[(k + 1) & 3] *
                                  __int_as_float((127 - knext) << 23);

                K += kcur;
                const float sc_cur = __int_as_float((127 - kcur) << 23);

                // matvec: acc = sum_i w_i * E[i,j], 12 LDS.128 + 24 FFMA2
                const ulonglong2* w2 = (const ulonglong2*)sh_w[p];
                unsigned long long a0 = 0ull, a1 = 0ull, a2 = 0ull, a3 = 0ull;
#pragma unroll
                for (int q = 0; q < LN / 4; q++) {
                    const ulonglong2 wq = w2[q];
                    switch (q & 1) {
                      case 0:
                        FMA_F32X2(a0, wq.x, Ep[2 * q],     a0);
                        FMA_F32X2(a1, wq.y, Ep[2 * q + 1], a1);
                        break;
                      default:
                        FMA_F32X2(a2, wq.x, Ep[2 * q],     a2);
                        FMA_F32X2(a3, wq.y, Ep[2 * q + 1], a3);
                        break;
                    }
                }
                unsigned long long s01, s23, s;
                ADD_F32X2_(s01, a0, a1);
                ADD_F32X2_(s23, a2, a3);
                ADD_F32X2_(s, s01, s23);
                float slo, shi;
                UNPACK_F32X2_(slo, shi, s);
                const float accv = slo + shi;

                u = msk ? accv : u * sc_cur;

                // publish exponent of u_0 (thread 0); consumed next step
                if (tid == 0) sh_k[p] = (__float_as_int(u) >> 23) - 127;

                w = u * esn;            // short tail: FSEL + 1 FMUL
                kcur = knext;

                if (t0 + 4 < TN) {
                    es[k] = __expf(scp[(t0 + 4 + k) * LN]);
                    mb[k] = mp[t0 + 4 + k];
                }
            }
        }

        if (tid == END_I)
            sh_fs = (float)K * 0.6931471805599453f + logf(u);
    } else {
        // ---------------- tg group (gold-path energy) ----------------
        const int tl   = tid - 64;          // 0..63
        const int lane = tl & 31;
        const int wi   = tl >> 5;

        // gold_target declared int64 but JAX (x64 off) materializes int32 — detect:
        // true int64 => every odd 32-bit word is 0 (labels < 48).
        const int* g32 = (const int*)gold_raw;
        if (tl == 0) {
            int all0 = 1;
            for (int q = 0; q < 64; q++) all0 &= (g32[2 * q + 1] == 0);
            s_is64 = all0;
        }
        BAR_TG();
        const int is64 = s_is64;

        float sum = 0.f;
#pragma unroll
        for (int t = tl; t < TN; t += 64) {
            const long long li = (long long)b * TN + t;
            const int g = is64 ? g32[2 * li] : g32[li];   // little-endian low word
            const float v = scores[li * LN] + trans[g];   // crf[t+1,b,0,g]
            if (mask[li]) sum += v;
        }
        if (tl == 0) sum += trans[START_I];  // t=0 term: trans[0][START]

        // deterministic warp reduction
        sum += __shfl_xor_sync(0xffffffffu, sum, 16);
        sum += __shfl_xor_sync(0xffffffffu, sum, 8);
        sum += __shfl_xor_sync(0xffffffffu, sum, 4);
        sum += __shfl_xor_sync(0xffffffffu, sum, 2);
        sum += __shfl_xor_sync(0xffffffffu, sum, 1);
        if (lane == 0) sh_tgp[wi] = sum;
    }

    __syncthreads();   // join scan + tg groups

    if (tid == 0) {
        g_val[b] = sh_fs - (sh_tgp[0] + sh_tgp[1]);
        __threadfence();
        const unsigned r = atomicAdd(&g_done, 1u);
        if (r == BN - 1) {            // last block: deterministic final combine
            float acc = 0.f;
            for (int i = 0; i < BN; i++) acc += g_val[i];
            out[0] = acc / (float)BN;
            g_done = 0u;              // reset for next graph replay
        }
    }
}

extern "C" void kernel_launch(void* const* d_in, const int* in_sizes, int n_in,
                              void* d_out, int out_size)
{
    const float* scores = (const float*)d_in[0];
    const void*  gold   = (const void*)d_in[1];
    const int*   mask   = (const int*)d_in[2];
    const float* trans  = (const float*)d_in[3];
    float*       out    = (float*)d_out;

    crf_fused_kernel<<<BN, 128>>>(scores, gold, mask, trans, out);
}